// round 6
// baseline (speedup 1.0000x reference)
#include <cuda_runtime.h>
#include <cuda_bf16.h>
#include <math.h>
#include <stdint.h>

// Problem constants
#define Bc 4
#define Tc 4096
#define Ec 1024
#define Hc 16
#define Sc 64
#define Dc 64
#define Mc (Bc * Tc)   // 16384

// ---------------- scratch (device globals: alloc-free rule) ----------------
__device__ float g_q[(size_t)Mc * Ec];
__device__ float g_k[(size_t)Mc * Ec];
__device__ float g_v[(size_t)Mc * Ec];
__device__ float g_ro[(size_t)Mc * Ec];
__device__ float g_slot[Bc * Hc * Sc * Dc];     // [b][h][s][d]
__device__ float g_cos[Tc * 32];
__device__ float g_sin[Tc * 32];

// int8 split operands
__device__ int8_t g_xh[(size_t)Mc * Ec];
__device__ int8_t g_xl[(size_t)Mc * Ec];
__device__ int8_t g_roh[(size_t)Mc * Ec];
__device__ int8_t g_rol[(size_t)Mc * Ec];
__device__ int8_t g_wh8[4][(size_t)Ec * Ec];
__device__ int8_t g_wl8[4][(size_t)Ec * Ec];
__device__ float g_sx[Mc];
__device__ float g_sro[Mc];
__device__ float g_sw[4][Ec];

// ======================= helpers =======================
__device__ __forceinline__ uint32_t smem_u32(const void* p) {
    uint32_t a;
    asm("{ .reg .u64 t; cvta.to.shared.u64 t, %1; cvt.u32.u64 %0, t; }" : "=r"(a) : "l"(p));
    return a;
}
#define SWZ64(off) ((off) ^ (((off) >> 3) & 0x30))

__device__ __forceinline__ void cp_async16(uint32_t dst, const void* src) {
    asm volatile("cp.async.cg.shared.global [%0], [%1], 16;" :: "r"(dst), "l"(src) : "memory");
}
__device__ __forceinline__ void ldsm4(uint32_t* r, uint32_t addr) {
    asm volatile("ldmatrix.sync.aligned.m8n8.x4.shared.b16 {%0,%1,%2,%3}, [%4];"
        : "=r"(r[0]), "=r"(r[1]), "=r"(r[2]), "=r"(r[3]) : "r"(addr));
}
// s8 x s8 -> s32, m16n8k32
__device__ __forceinline__ void imma16832(int* d, const uint32_t* a, uint32_t b0, uint32_t b1) {
    asm volatile("mma.sync.aligned.m16n8k32.row.col.s32.s8.s8.s32 "
        "{%0,%1,%2,%3}, {%4,%5,%6,%7}, {%8,%9}, {%0,%1,%2,%3};"
        : "+r"(d[0]), "+r"(d[1]), "+r"(d[2]), "+r"(d[3])
        : "r"(a[0]), "r"(a[1]), "r"(a[2]), "r"(a[3]), "r"(b0), "r"(b1));
}

// ---------------- rope tables ----------------
__global__ void rope_table_kernel(float* __restrict__ ct, float* __restrict__ st) {
    int t = blockIdx.x;
    int i = threadIdx.x;
    double p = pow(10000.0, -(double)i / 32.0);
    float ang = (float)t * (float)p;
    ct[t * 32 + i] = cosf(ang);
    st[t * 32 + i] = sinf(ang);
}

__global__ void zero_kernel(float* __restrict__ p, int n) {
    int i = blockIdx.x * 256 + threadIdx.x;
    if (i < n) p[i] = 0.0f;
}

// ---------------- fp32 -> int8 two-level quant: v = sigma*(128*h + l) ----------------
// one warp per row of 1024 elements
__global__ void quant_kernel(const float* __restrict__ in,
                             int8_t* __restrict__ hi, int8_t* __restrict__ lo,
                             float* __restrict__ scale) {
    const int row = blockIdx.x * 8 + (threadIdx.x >> 5);
    const int l = threadIdx.x & 31;
    const float* rp = in + (size_t)row * 1024;

    float4 v[8];
    float mx = 0.0f;
#pragma unroll
    for (int g = 0; g < 8; g++) {
        v[g] = ((const float4*)rp)[g * 32 + l];
        mx = fmaxf(mx, fmaxf(fmaxf(fabsf(v[g].x), fabsf(v[g].y)),
                             fmaxf(fabsf(v[g].z), fabsf(v[g].w))));
    }
#pragma unroll
    for (int off = 16; off; off >>= 1) mx = fmaxf(mx, __shfl_xor_sync(0xffffffffu, mx, off));
    const float sigma = fmaxf(mx, 1e-30f) * (1.0f / 16256.0f);   // 127*128
    const float inv = 1.0f / sigma;

#pragma unroll
    for (int g = 0; g < 8; g++) {
        float f[4] = {v[g].x * inv, v[g].y * inv, v[g].z * inv, v[g].w * inv};
        char hch[4], lch[4];
#pragma unroll
        for (int j = 0; j < 4; j++) {
            float fh = rintf(f[j] * (1.0f / 128.0f));
            int hq = (int)fh;
            int lq = __float2int_rn(f[j] - 128.0f * fh);
            hch[j] = (char)hq;
            lch[j] = (char)lq;
        }
        *(char4*)(hi + (size_t)row * 1024 + g * 128 + l * 4) = make_char4(hch[0], hch[1], hch[2], hch[3]);
        *(char4*)(lo + (size_t)row * 1024 + g * 128 + l * 4) = make_char4(lch[0], lch[1], lch[2], lch[3]);
    }
    if (l == 0) scale[row] = sigma;
}

// ======================= split-int8 NT GEMM on IMMA (mma.sync) =======================
// C[m][n] = sA[m]*sB[n]*128*(128*HH + (HL+LH)). Block tile 128x128, K-chunk 64 int8
// (64B rows, SW64). 8 warps 4(m)x2(n); warp 32x64. 3 stages x 4 tiles x 8KB = 96KB.
#define NSTAGES 3
#define TILE_B 8192
#define STAGE_B (4 * TILE_B)
#define GEMM_SMEM (NSTAGES * STAGE_B)
#define NCHUNK 16

template <int ROPE>
__global__ void __launch_bounds__(256, 1)
tc_gemm(const int8_t* __restrict__ Ahi, const int8_t* __restrict__ Alo,
        const int8_t* __restrict__ Bhi, const int8_t* __restrict__ Blo,
        const float* __restrict__ sA, const float* __restrict__ sB,
        float* __restrict__ C,
        const float* __restrict__ ctab, const float* __restrict__ stab) {
    extern __shared__ char smem[];
    __shared__ float s_sa[128];
    __shared__ float s_sb[128];
    const uint32_t sb = smem_u32(smem);
    const int tid = threadIdx.x;
    const int wid = tid >> 5, lane = tid & 31;
    const int wm = wid >> 1;            // 0..3 (m)
    const int wn = wid & 1;             // 0..1 (n)
    const int bn = blockIdx.x, bm = blockIdx.y;

    if (tid < 128) {
        s_sa[tid] = sA[bm * 128 + tid];
        s_sb[tid] = sB[bn * 128 + tid];
    }

    const int8_t* bp[4];
    bp[0] = Ahi + (size_t)bm * 128 * 1024;
    bp[1] = Alo + (size_t)bm * 128 * 1024;
    bp[2] = Bhi + (size_t)bn * 128 * 1024;
    bp[3] = Blo + (size_t)bn * 128 * 1024;

    // 128 rows x 64B per tile per chunk: 512 cp.async16 per tile-pair set
    auto load_chunk = [&](int c, int st) {
        const uint32_t stbase = sb + st * STAGE_B;
        const int k0 = c * 64;
#pragma unroll
        for (int i = 0; i < 8; i++) {
            const int sub = i >> 1;
            const int rc = (i & 1) * 256 + tid;   // 0..511
            const int row = rc >> 2;
            const int seg = rc & 3;
            uint32_t off = (uint32_t)row * 64 + seg * 16;
            uint32_t dst = stbase + sub * TILE_B + SWZ64(off);
            cp_async16(dst, bp[sub] + (size_t)row * 1024 + (k0 + seg * 16));
        }
    };

    int hh[2][8][4], mix[2][8][4];
#pragma unroll
    for (int mt = 0; mt < 2; mt++)
#pragma unroll
        for (int nt = 0; nt < 8; nt++)
#pragma unroll
            for (int r = 0; r < 4; r++) { hh[mt][nt][r] = 0; mix[mt][nt][r] = 0; }

    load_chunk(0, 0); asm volatile("cp.async.commit_group;" ::: "memory");
    load_chunk(1, 1); asm volatile("cp.async.commit_group;" ::: "memory");

    const int lrow = lane & 15;
    const uint32_t lkb = (uint32_t)(lane >> 4) * 16;   // 16B half select
    uint32_t aswz[2], bswz[4];
#pragma unroll
    for (int mt = 0; mt < 2; mt++)
        aswz[mt] = SWZ64((uint32_t)(wm * 32 + mt * 16 + lrow) * 64);
#pragma unroll
    for (int nq = 0; nq < 4; nq++)
        bswz[nq] = SWZ64((uint32_t)(wn * 64 + nq * 16 + lrow) * 64);

    for (int c = 0; c < NCHUNK; c++) {
        const uint32_t stbase = sb + (uint32_t)(c % 3) * STAGE_B;
        asm volatile("cp.async.wait_group 1;" ::: "memory");
        __syncthreads();

        const uint32_t aHi = stbase;
        const uint32_t aLo = stbase + TILE_B;
        const uint32_t bHi = stbase + 2 * TILE_B;
        const uint32_t bLo = stbase + 3 * TILE_B;

#pragma unroll
        for (int ks = 0; ks < 2; ks++) {     // two k32 steps per 64B chunk
            const uint32_t kb = (uint32_t)ks * 32 ^ lkb;
            uint32_t ah[2][4], al[2][4];
#pragma unroll
            for (int mt = 0; mt < 2; mt++) {
                ldsm4(ah[mt], aHi + (aswz[mt] ^ kb));
                ldsm4(al[mt], aLo + (aswz[mt] ^ kb));
            }
#pragma unroll
            for (int nq = 0; nq < 4; nq++) {
                uint32_t rh[4], rl[4];
                ldsm4(rh, bHi + (bswz[nq] ^ kb));
                ldsm4(rl, bLo + (bswz[nq] ^ kb));
                // pass-major order to break accumulator dependency chains
#pragma unroll
                for (int mt = 0; mt < 2; mt++) {
                    imma16832(hh[mt][nq * 2],      ah[mt], rh[0], rh[2]);
                    imma16832(hh[mt][nq * 2 + 1],  ah[mt], rh[1], rh[3]);
                }
#pragma unroll
                for (int mt = 0; mt < 2; mt++) {
                    imma16832(mix[mt][nq * 2],     ah[mt], rl[0], rl[2]);
                    imma16832(mix[mt][nq * 2 + 1], ah[mt], rl[1], rl[3]);
                }
#pragma unroll
                for (int mt = 0; mt < 2; mt++) {
                    imma16832(mix[mt][nq * 2],     al[mt], rh[0], rh[2]);
                    imma16832(mix[mt][nq * 2 + 1], al[mt], rh[1], rh[3]);
                }
            }
        }
        if (c + 2 < NCHUNK) load_chunk(c + 2, (c + 2) % 3);
        asm volatile("cp.async.commit_group;" ::: "memory");
    }
    __syncthreads();

    // ---- epilogue: dequant -> (RoPE) -> smem stage -> coalesced store ----
    float* stg = (float*)smem;          // 128 x 132 floats = 67.6KB < 96KB
    const int qr = lane >> 2;           // 0..7
    const int qc = (lane & 3) * 2;      // 0,2,4,6
#pragma unroll
    for (int mt = 0; mt < 2; mt++) {
#pragma unroll
        for (int nt = 0; nt < 8; nt++) {
            const int c0 = wn * 64 + nt * 8 + qc;
            const float sb0 = s_sb[c0] * 128.0f;
            const float sb1 = s_sb[c0 + 1] * 128.0f;
#pragma unroll
            for (int half = 0; half < 2; half++) {
                const int r = wm * 32 + mt * 16 + half * 8 + qr;
                const float sa = s_sa[r];
                float e  = sa * sb0 * (128.0f * (float)hh[mt][nt][half * 2]     + (float)mix[mt][nt][half * 2]);
                float od = sa * sb1 * (128.0f * (float)hh[mt][nt][half * 2 + 1] + (float)mix[mt][nt][half * 2 + 1]);
                if (ROPE) {
                    const int t = (bm * 128 + r) & (Tc - 1);
                    const int i0 = (nt * 8 + qc) & 31;
                    const float cc0 = ctab[t * 32 + i0], ss0 = stab[t * 32 + i0];
                    const float cc1 = ctab[t * 32 + i0 + 1], ss1 = stab[t * 32 + i0 + 1];
                    const float ne = e * cc0 - od * ss0;
                    const float no = od * cc1 + e * ss1;
                    e = ne; od = no;
                }
                stg[r * 132 + c0] = e;
                stg[r * 132 + c0 + 1] = od;
            }
        }
    }
    __syncthreads();
#pragma unroll
    for (int i = 0; i < 16; i++) {
        const int idx = i * 256 + tid;
        const int r = idx >> 5, c4 = (idx & 31) * 4;
        *(float4*)&C[(size_t)(bm * 128 + r) * 1024 + bn * 128 + c4] =
            *(const float4*)&stg[r * 132 + c4];
    }
}

// ---------------- write path (unchanged, passing) ----------------
__global__ __launch_bounds__(256, 1)
void write_kernel(const float* __restrict__ gk, const float* __restrict__ gv,
                  const float* __restrict__ slot_keys, float* __restrict__ gslot) {
    __shared__ float sk[64 * 65];
    __shared__ float kvs[8][2][64];

    const int b = blockIdx.z, h = blockIdx.y, chunk = blockIdx.x;
    const int tid = threadIdx.x, w = tid >> 5, l = tid & 31;

    for (int idx = tid; idx < 4096; idx += 256) {
        int s = idx >> 6, d = idx & 63;
        sk[s * 65 + d] = slot_keys[((size_t)h * 64 + s) * 64 + d];
    }
    __syncthreads();

    float accL[64], accH[64];
#pragma unroll
    for (int d = 0; d < 64; d++) { accL[d] = 0.0f; accH[d] = 0.0f; }

    const float* skL = &sk[l * 65];
    const float* skH = &sk[(l + 32) * 65];
    const int t0 = chunk * 512 + w * 64;

    for (int tt = 0; tt < 64; tt++) {
        int t = t0 + tt;
        size_t row = ((size_t)b * Tc + t) * 1024 + h * 64;
        kvs[w][0][l] = gk[row + l];       kvs[w][0][l + 32] = gk[row + l + 32];
        kvs[w][1][l] = gv[row + l];       kvs[w][1][l + 32] = gv[row + l + 32];
        __syncwarp();

        float lo = 0.0f, hi = 0.0f;
#pragma unroll
        for (int d = 0; d < 64; d++) {
            float kd = kvs[w][0][d];
            lo += kd * skL[d];
            hi += kd * skH[d];
        }
        lo *= 0.125f; hi *= 0.125f;

        float mx = fmaxf(lo, hi);
#pragma unroll
        for (int off = 16; off; off >>= 1) mx = fmaxf(mx, __shfl_xor_sync(0xffffffffu, mx, off));
        float el = __expf(lo - mx), eh = __expf(hi - mx);
        float sm = el + eh;
#pragma unroll
        for (int off = 16; off; off >>= 1) sm += __shfl_xor_sync(0xffffffffu, sm, off);
        float inv = 1.0f / sm;
        float wl = el * inv, wh = eh * inv;

#pragma unroll
        for (int d = 0; d < 64; d++) {
            float vd = kvs[w][1][d];
            accL[d] += wl * vd;
            accH[d] += wh * vd;
        }
        __syncwarp();
    }

    __syncthreads();
    for (int idx = tid; idx < 64 * 65; idx += 256) sk[idx] = 0.0f;
    __syncthreads();
#pragma unroll
    for (int d = 0; d < 64; d++) {
        atomicAdd(&sk[l * 65 + d], accL[d]);
        atomicAdd(&sk[(l + 32) * 65 + d], accH[d]);
    }
    __syncthreads();
    float* base = gslot + ((size_t)(b * Hc + h)) * 4096;
    for (int idx = tid; idx < 4096; idx += 256) {
        int s = idx >> 6, d = idx & 63;
        atomicAdd(&base[idx], sk[s * 65 + d]);
    }
}

// ---------------- read path (unchanged, passing) ----------------
__global__ __launch_bounds__(256, 2)
void read_kernel(const float* __restrict__ gq, const float* __restrict__ gslot,
                 float* __restrict__ gro) {
    __shared__ float ss[64 * 65];
    __shared__ float qs[8][64];
    __shared__ float ws[8][64];

    const int b = blockIdx.z, h = blockIdx.y, chunk = blockIdx.x;
    const int tid = threadIdx.x, w = tid >> 5, l = tid & 31;

    const float* base = gslot + ((size_t)(b * Hc + h)) * 4096;
    const float invT = 1.0f / (float)Tc;
    for (int idx = tid; idx < 4096; idx += 256) {
        int s = idx >> 6, d = idx & 63;
        ss[s * 65 + d] = base[idx] * invT;
    }
    __syncthreads();

    const float* ssL = &ss[l * 65];
    const float* ssH = &ss[(l + 32) * 65];
    const int t0 = chunk * 512 + w * 64;

    for (int tt = 0; tt < 64; tt++) {
        int t = t0 + tt;
        size_t row = ((size_t)b * Tc + t) * 1024 + h * 64;
        qs[w][l] = gq[row + l];  qs[w][l + 32] = gq[row + l + 32];
        __syncwarp();

        float lo = 0.0f, hi = 0.0f;
#pragma unroll
        for (int d = 0; d < 64; d++) {
            float qd = qs[w][d];
            lo += qd * ssL[d];
            hi += qd * ssH[d];
        }
        lo *= 0.125f; hi *= 0.125f;

        float mx = fmaxf(lo, hi);
#pragma unroll
        for (int off = 16; off; off >>= 1) mx = fmaxf(mx, __shfl_xor_sync(0xffffffffu, mx, off));
        float el = __expf(lo - mx), eh = __expf(hi - mx);
        float sm = el + eh;
#pragma unroll
        for (int off = 16; off; off >>= 1) sm += __shfl_xor_sync(0xffffffffu, sm, off);
        float inv = 1.0f / sm;
        ws[w][l] = el * inv;  ws[w][l + 32] = eh * inv;
        __syncwarp();

        float oL = 0.0f, oH = 0.0f;
#pragma unroll
        for (int s = 0; s < 64; s++) {
            float wv = ws[w][s];
            oL += wv * ss[s * 65 + l];
            oH += wv * ss[s * 65 + l + 32];
        }
        gro[row + l] = oL;
        gro[row + l + 32] = oH;
        __syncwarp();
    }
}

// ---------------- launch ----------------
extern "C" void kernel_launch(void* const* d_in, const int* in_sizes, int n_in,
                              void* d_out, int out_size) {
    (void)in_sizes; (void)n_in; (void)out_size;
    const float* x         = (const float*)d_in[0];
    const float* Wq        = (const float*)d_in[1];
    const float* Wk        = (const float*)d_in[2];
    const float* Wv        = (const float*)d_in[3];
    const float* Wout      = (const float*)d_in[4];
    const float* slot_keys = (const float*)d_in[5];
    float* out = (float*)d_out;

    float *pq, *pk, *pv, *pro, *pslot, *pcos, *psin;
    cudaGetSymbolAddress((void**)&pq,    g_q);
    cudaGetSymbolAddress((void**)&pk,    g_k);
    cudaGetSymbolAddress((void**)&pv,    g_v);
    cudaGetSymbolAddress((void**)&pro,   g_ro);
    cudaGetSymbolAddress((void**)&pslot, g_slot);
    cudaGetSymbolAddress((void**)&pcos,  g_cos);
    cudaGetSymbolAddress((void**)&psin,  g_sin);

    int8_t *xh, *xl, *roh, *rol, *wh8, *wl8;
    float *sx, *sro, *sw;
    cudaGetSymbolAddress((void**)&xh,  g_xh);
    cudaGetSymbolAddress((void**)&xl,  g_xl);
    cudaGetSymbolAddress((void**)&roh, g_roh);
    cudaGetSymbolAddress((void**)&rol, g_rol);
    cudaGetSymbolAddress((void**)&wh8, g_wh8);
    cudaGetSymbolAddress((void**)&wl8, g_wl8);
    cudaGetSymbolAddress((void**)&sx,  g_sx);
    cudaGetSymbolAddress((void**)&sro, g_sro);
    cudaGetSymbolAddress((void**)&sw,  g_sw);
    const size_t WSZ = (size_t)Ec * Ec;

    cudaFuncSetAttribute(tc_gemm<0>, cudaFuncAttributeMaxDynamicSharedMemorySize, GEMM_SMEM);
    cudaFuncSetAttribute(tc_gemm<1>, cudaFuncAttributeMaxDynamicSharedMemorySize, GEMM_SMEM);

    rope_table_kernel<<<Tc, 32>>>(pcos, psin);

    // quantize inputs (one warp per row; 8 rows per block)
    quant_kernel<<<Mc / 8, 256>>>(x, xh, xl, sx);
    quant_kernel<<<Ec / 8, 256>>>(Wq,   wh8 + 0 * WSZ, wl8 + 0 * WSZ, sw + 0 * Ec);
    quant_kernel<<<Ec / 8, 256>>>(Wk,   wh8 + 1 * WSZ, wl8 + 1 * WSZ, sw + 1 * Ec);
    quant_kernel<<<Ec / 8, 256>>>(Wv,   wh8 + 2 * WSZ, wl8 + 2 * WSZ, sw + 2 * Ec);
    quant_kernel<<<Ec / 8, 256>>>(Wout, wh8 + 3 * WSZ, wl8 + 3 * WSZ, sw + 3 * Ec);

    dim3 gg(Ec / 128, Mc / 128);   // (8, 128)
    tc_gemm<1><<<gg, 256, GEMM_SMEM>>>(xh, xl, wh8 + 0 * WSZ, wl8 + 0 * WSZ, sx, sw + 0 * Ec, pq, pcos, psin);
    tc_gemm<1><<<gg, 256, GEMM_SMEM>>>(xh, xl, wh8 + 1 * WSZ, wl8 + 1 * WSZ, sx, sw + 1 * Ec, pk, pcos, psin);
    tc_gemm<0><<<gg, 256, GEMM_SMEM>>>(xh, xl, wh8 + 2 * WSZ, wl8 + 2 * WSZ, sx, sw + 2 * Ec, pv, pcos, psin);

    zero_kernel<<<(Bc * Hc * Sc * Dc + 255) / 256, 256>>>(pslot, Bc * Hc * Sc * Dc);

    write_kernel<<<dim3(8, Hc, Bc), 256>>>(pk, pv, slot_keys, pslot);
    read_kernel<<<dim3(8, Hc, Bc), 256>>>(pq, pslot, pro);

    quant_kernel<<<Mc / 8, 256>>>(pro, roh, rol, sro);
    tc_gemm<0><<<gg, 256, GEMM_SMEM>>>(roh, rol, wh8 + 3 * WSZ, wl8 + 3 * WSZ, sro, sw + 3 * Ec, out, pcos, psin);
}

// round 12
// speedup vs baseline: 2.6241x; 2.6241x over previous
#include <cuda_runtime.h>
#include <cuda_bf16.h>
#include <cuda_fp16.h>
#include <math.h>
#include <stdint.h>

// Problem constants
#define Bc 4
#define Tc 4096
#define Ec 1024
#define Hc 16
#define Sc 64
#define Dc 64
#define Mc (Bc * Tc)   // 16384

// ---------------- scratch (device globals: alloc-free rule) ----------------
__device__ float g_q[(size_t)Mc * Ec];
__device__ float g_k[(size_t)Mc * Ec];
__device__ float g_v[(size_t)Mc * Ec];
__device__ float g_ro[(size_t)Mc * Ec];
__device__ float g_slot[Bc * Hc * Sc * Dc];     // [b][h][s][d]
__device__ float g_cos[Tc * 32];
__device__ float g_sin[Tc * 32];

// fp16 single-pass operands (QKV)
__device__ __half g_xf[(size_t)Mc * Ec];
__device__ __half g_wf[3][(size_t)Ec * Ec];
// bf16 split operands (Wout path)
__device__ __nv_bfloat16 g_rohi[(size_t)Mc * Ec];
__device__ __nv_bfloat16 g_rolo[(size_t)Mc * Ec];
__device__ __nv_bfloat16 g_whi[(size_t)Ec * Ec];
__device__ __nv_bfloat16 g_wlo[(size_t)Ec * Ec];

// ======================= helpers =======================
__device__ __forceinline__ uint32_t smem_u32(const void* p) {
    uint32_t a;
    asm("{ .reg .u64 t; cvta.to.shared.u64 t, %1; cvt.u32.u64 %0, t; }" : "=r"(a) : "l"(p));
    return a;
}
#define SWZ64(off) ((off) ^ (((off) >> 3) & 0x30))

__device__ __forceinline__ void cp_async16(uint32_t dst, const void* src) {
    asm volatile("cp.async.cg.shared.global [%0], [%1], 16;" :: "r"(dst), "l"(src) : "memory");
}
__device__ __forceinline__ void ldsm4(uint32_t* r, uint32_t addr) {
    asm volatile("ldmatrix.sync.aligned.m8n8.x4.shared.b16 {%0,%1,%2,%3}, [%4];"
        : "=r"(r[0]), "=r"(r[1]), "=r"(r[2]), "=r"(r[3]) : "r"(addr));
}
__device__ __forceinline__ void mma_bf16(float* d, const uint32_t* a, uint32_t b0, uint32_t b1) {
    asm volatile("mma.sync.aligned.m16n8k16.row.col.f32.bf16.bf16.f32 "
        "{%0,%1,%2,%3}, {%4,%5,%6,%7}, {%8,%9}, {%0,%1,%2,%3};"
        : "+f"(d[0]), "+f"(d[1]), "+f"(d[2]), "+f"(d[3])
        : "r"(a[0]), "r"(a[1]), "r"(a[2]), "r"(a[3]), "r"(b0), "r"(b1));
}
__device__ __forceinline__ void mma_f16(float* d, const uint32_t* a, uint32_t b0, uint32_t b1) {
    asm volatile("mma.sync.aligned.m16n8k16.row.col.f32.f16.f16.f32 "
        "{%0,%1,%2,%3}, {%4,%5,%6,%7}, {%8,%9}, {%0,%1,%2,%3};"
        : "+f"(d[0]), "+f"(d[1]), "+f"(d[2]), "+f"(d[3])
        : "r"(a[0]), "r"(a[1]), "r"(a[2]), "r"(a[3]), "r"(b0), "r"(b1));
}

// ---------------- rope tables ----------------
__global__ void rope_table_kernel(float* __restrict__ ct, float* __restrict__ st) {
    int t = blockIdx.x;
    int i = threadIdx.x;
    double p = pow(10000.0, -(double)i / 32.0);
    float ang = (float)t * (float)p;
    ct[t * 32 + i] = cosf(ang);
    st[t * 32 + i] = sinf(ang);
}

__global__ void zero_kernel(float* __restrict__ p, int n) {
    int i = blockIdx.x * 256 + threadIdx.x;
    if (i < n) p[i] = 0.0f;
}

// ---------------- fp32 -> fp16 convert ----------------
__global__ void cvt_f16_kernel(const float* __restrict__ in, __half* __restrict__ out, int n4) {
    int i = blockIdx.x * 256 + threadIdx.x;
    if (i >= n4) return;
    float4 v = ((const float4*)in)[i];
    __align__(8) __half2 h[2];
    h[0] = __floats2half2_rn(v.x, v.y);
    h[1] = __floats2half2_rn(v.z, v.w);
    *(uint2*)(out + 4 * (size_t)i) = *(const uint2*)h;
}

// ---------------- fp32 -> bf16 hi/lo split ----------------
__global__ void split_kernel(const float* __restrict__ in,
                             __nv_bfloat16* __restrict__ hi,
                             __nv_bfloat16* __restrict__ lo, int n4) {
    int i = blockIdx.x * 256 + threadIdx.x;
    if (i >= n4) return;
    float4 v = ((const float4*)in)[i];
    float vv[4] = {v.x, v.y, v.z, v.w};
    __align__(8) __nv_bfloat16 h[4];
    __align__(8) __nv_bfloat16 l[4];
#pragma unroll
    for (int j = 0; j < 4; j++) {
        h[j] = __float2bfloat16_rn(vv[j]);
        l[j] = __float2bfloat16_rn(vv[j] - __bfloat162float(h[j]));
    }
    *(uint2*)(hi + 4 * (size_t)i) = *(const uint2*)h;
    *(uint2*)(lo + 4 * (size_t)i) = *(const uint2*)l;
}

// ======================= 1-pass fp16 NT GEMM (QKV) =======================
// C[m][n] = sum_k A[m][k]*B[n][k]. Block tile 128x128, K-chunk 32 (64B rows, SW64).
// 8 warps 4(m)x2(n); warp 32x64. Pipeline: 3 stages x 2 tiles x 8KB = 48KB.
// Epilogue staging needs 128*132*4 = 67584B -> smem sized to the max of the two.
#define T1_TILE 8192
#define T1_STAGE (2 * T1_TILE)
#define STG_BYTES (128 * 132 * 4)
#define GEMM1_SMEM (STG_BYTES > 3 * T1_STAGE ? STG_BYTES : 3 * T1_STAGE)   // 67584

template <int ROPE>
__global__ void __launch_bounds__(256, 2)
gemm1(const __half* __restrict__ A, const __half* __restrict__ B,
      float* __restrict__ C,
      const float* __restrict__ ctab, const float* __restrict__ stab) {
    extern __shared__ char smem[];
    const uint32_t sb = smem_u32(smem);
    const int tid = threadIdx.x;
    const int wid = tid >> 5, lane = tid & 31;
    const int wm = wid >> 1, wn = wid & 1;
    const int bn = blockIdx.x, bm = blockIdx.y;

    const __half* bpA = A + (size_t)bm * 128 * 1024;
    const __half* bpB = B + (size_t)bn * 128 * 1024;

    auto load_chunk = [&](int c, int st) {
        const uint32_t stbase = sb + st * T1_STAGE;
        const int k0 = c * 32;
#pragma unroll
        for (int i = 0; i < 4; i++) {
            const int sub = i >> 1;
            const int rc = (i & 1) * 256 + tid;   // 0..511
            const int row = rc >> 2;
            const int seg = rc & 3;
            uint32_t dst = stbase + sub * T1_TILE + SWZ64((uint32_t)row * 64 + seg * 16);
            const __half* src = (sub == 0 ? bpA : bpB) + (size_t)row * 1024 + (k0 + seg * 8);
            cp_async16(dst, src);
        }
    };

    float acc[2][8][4];
#pragma unroll
    for (int mt = 0; mt < 2; mt++)
#pragma unroll
        for (int nt = 0; nt < 8; nt++)
#pragma unroll
            for (int r = 0; r < 4; r++) acc[mt][nt][r] = 0.0f;

    load_chunk(0, 0); asm volatile("cp.async.commit_group;" ::: "memory");
    load_chunk(1, 1); asm volatile("cp.async.commit_group;" ::: "memory");

    const int lrow = lane & 15;
    const uint32_t lkb = (uint32_t)(lane >> 4) * 16;
    uint32_t aswz[2], bswz[4];
#pragma unroll
    for (int mt = 0; mt < 2; mt++)
        aswz[mt] = SWZ64((uint32_t)(wm * 32 + mt * 16 + lrow) * 64);
#pragma unroll
    for (int nq = 0; nq < 4; nq++)
        bswz[nq] = SWZ64((uint32_t)(wn * 64 + nq * 16 + lrow) * 64);

    for (int c = 0; c < 32; c++) {
        const uint32_t stbase = sb + (uint32_t)(c % 3) * T1_STAGE;
        asm volatile("cp.async.wait_group 1;" ::: "memory");
        __syncthreads();

        const uint32_t aB = stbase;
        const uint32_t bB = stbase + T1_TILE;
#pragma unroll
        for (int ks = 0; ks < 2; ks++) {
            const uint32_t kb = (uint32_t)ks * 32 ^ lkb;
            uint32_t af[2][4];
#pragma unroll
            for (int mt = 0; mt < 2; mt++) ldsm4(af[mt], aB + (aswz[mt] ^ kb));
#pragma unroll
            for (int nq = 0; nq < 4; nq++) {
                uint32_t rb[4];
                ldsm4(rb, bB + (bswz[nq] ^ kb));
#pragma unroll
                for (int mt = 0; mt < 2; mt++) {
                    mma_f16(acc[mt][nq * 2],     af[mt], rb[0], rb[2]);
                    mma_f16(acc[mt][nq * 2 + 1], af[mt], rb[1], rb[3]);
                }
            }
        }
        if (c + 2 < 32) load_chunk(c + 2, (c + 2) % 3);
        asm volatile("cp.async.commit_group;" ::: "memory");
    }
    __syncthreads();

    // epilogue
    float* stg = (float*)smem;
    const int qr = lane >> 2;
    const int qc = (lane & 3) * 2;
#pragma unroll
    for (int mt = 0; mt < 2; mt++) {
#pragma unroll
        for (int nt = 0; nt < 8; nt++) {
            const int c0 = wn * 64 + nt * 8 + qc;
#pragma unroll
            for (int half = 0; half < 2; half++) {
                const int r = wm * 32 + mt * 16 + half * 8 + qr;
                float e = acc[mt][nt][half * 2];
                float od = acc[mt][nt][half * 2 + 1];
                if (ROPE) {
                    const int t = (bm * 128 + r) & (Tc - 1);
                    const int i0 = (nt * 8 + qc) & 31;
                    const float cc0 = ctab[t * 32 + i0], ss0 = stab[t * 32 + i0];
                    const float cc1 = ctab[t * 32 + i0 + 1], ss1 = stab[t * 32 + i0 + 1];
                    const float ne = e * cc0 - od * ss0;
                    const float no = od * cc1 + e * ss1;
                    e = ne; od = no;
                }
                stg[r * 132 + c0] = e;
                stg[r * 132 + c0 + 1] = od;
            }
        }
    }
    __syncthreads();
#pragma unroll
    for (int i = 0; i < 16; i++) {
        const int idx = i * 256 + tid;
        const int r = idx >> 5, c4 = (idx & 31) * 4;
        *(float4*)&C[(size_t)(bm * 128 + r) * 1024 + bn * 128 + c4] =
            *(const float4*)&stg[r * 132 + c4];
    }
}

// ======================= 3-pass bf16 split NT GEMM (Wout; round-5 validated) ============
#define NSTAGES 3
#define TILE_B 8192
#define STAGE_B (4 * TILE_B)
#define GEMM3_SMEM (NSTAGES * STAGE_B)   // 96KB > 67.6KB staging: safe

__global__ void __launch_bounds__(256, 2)
gemm3(const __nv_bfloat16* __restrict__ Ahi, const __nv_bfloat16* __restrict__ Alo,
      const __nv_bfloat16* __restrict__ Bhi, const __nv_bfloat16* __restrict__ Blo,
      float* __restrict__ C) {
    extern __shared__ char smem[];
    const uint32_t sb = smem_u32(smem);
    const int tid = threadIdx.x;
    const int wid = tid >> 5, lane = tid & 31;
    const int wm = wid >> 1, wn = wid & 1;
    const int bn = blockIdx.x, bm = blockIdx.y;

    const __nv_bfloat16* bp[4];
    bp[0] = Ahi + (size_t)bm * 128 * 1024;
    bp[1] = Alo + (size_t)bm * 128 * 1024;
    bp[2] = Bhi + (size_t)bn * 128 * 1024;
    bp[3] = Blo + (size_t)bn * 128 * 1024;

    auto load_chunk = [&](int c, int st) {
        const uint32_t stbase = sb + st * STAGE_B;
        const int k0 = c * 32;
#pragma unroll
        for (int i = 0; i < 8; i++) {
            const int sub = i >> 1;
            const int rc = (i & 1) * 256 + tid;
            const int row = rc >> 2;
            const int seg = rc & 3;
            uint32_t dst = stbase + sub * TILE_B + SWZ64((uint32_t)row * 64 + seg * 16);
            cp_async16(dst, bp[sub] + (size_t)row * 1024 + (k0 + seg * 8));
        }
    };

    float acc[2][8][4];
#pragma unroll
    for (int mt = 0; mt < 2; mt++)
#pragma unroll
        for (int nt = 0; nt < 8; nt++)
#pragma unroll
            for (int r = 0; r < 4; r++) acc[mt][nt][r] = 0.0f;

    load_chunk(0, 0); asm volatile("cp.async.commit_group;" ::: "memory");
    load_chunk(1, 1); asm volatile("cp.async.commit_group;" ::: "memory");

    const int lrow = lane & 15;
    const uint32_t lkb = (uint32_t)(lane >> 4) * 16;
    uint32_t aswz[2], bswz[4];
#pragma unroll
    for (int mt = 0; mt < 2; mt++)
        aswz[mt] = SWZ64((uint32_t)(wm * 32 + mt * 16 + lrow) * 64);
#pragma unroll
    for (int nq = 0; nq < 4; nq++)
        bswz[nq] = SWZ64((uint32_t)(wn * 64 + nq * 16 + lrow) * 64);

    for (int c = 0; c < 32; c++) {
        const uint32_t stbase = sb + (uint32_t)(c % 3) * STAGE_B;
        asm volatile("cp.async.wait_group 1;" ::: "memory");
        __syncthreads();

        const uint32_t aHi = stbase;
        const uint32_t aLo = stbase + TILE_B;
        const uint32_t bHi = stbase + 2 * TILE_B;
        const uint32_t bLo = stbase + 3 * TILE_B;

#pragma unroll
        for (int ks = 0; ks < 2; ks++) {
            const uint32_t kb = (uint32_t)ks * 32 ^ lkb;
            uint32_t ah[2][4], al[2][4];
#pragma unroll
            for (int mt = 0; mt < 2; mt++) {
                ldsm4(ah[mt], aHi + (aswz[mt] ^ kb));
                ldsm4(al[mt], aLo + (aswz[mt] ^ kb));
            }
#pragma unroll
            for (int nq = 0; nq < 4; nq++) {
                uint32_t rh[4], rl[4];
                ldsm4(rh, bHi + (bswz[nq] ^ kb));
                ldsm4(rl, bLo + (bswz[nq] ^ kb));
#pragma unroll
                for (int mt = 0; mt < 2; mt++) {
                    mma_bf16(acc[mt][nq * 2],     ah[mt], rh[0], rh[2]);
                    mma_bf16(acc[mt][nq * 2],     ah[mt], rl[0], rl[2]);
                    mma_bf16(acc[mt][nq * 2],     al[mt], rh[0], rh[2]);
                    mma_bf16(acc[mt][nq * 2 + 1], ah[mt], rh[1], rh[3]);
                    mma_bf16(acc[mt][nq * 2 + 1], ah[mt], rl[1], rl[3]);
                    mma_bf16(acc[mt][nq * 2 + 1], al[mt], rh[1], rh[3]);
                }
            }
        }
        if (c + 2 < 32) load_chunk(c + 2, (c + 2) % 3);
        asm volatile("cp.async.commit_group;" ::: "memory");
    }
    __syncthreads();

    float* stg = (float*)smem;
    const int qr = lane >> 2;
    const int qc = (lane & 3) * 2;
#pragma unroll
    for (int mt = 0; mt < 2; mt++) {
#pragma unroll
        for (int nt = 0; nt < 8; nt++) {
            const int c0 = wn * 64 + nt * 8 + qc;
#pragma unroll
            for (int half = 0; half < 2; half++) {
                const int r = wm * 32 + mt * 16 + half * 8 + qr;
                stg[r * 132 + c0] = acc[mt][nt][half * 2];
                stg[r * 132 + c0 + 1] = acc[mt][nt][half * 2 + 1];
            }
        }
    }
    __syncthreads();
#pragma unroll
    for (int i = 0; i < 16; i++) {
        const int idx = i * 256 + tid;
        const int r = idx >> 5, c4 = (idx & 31) * 4;
        *(float4*)&C[(size_t)(bm * 128 + r) * 1024 + bn * 128 + c4] =
            *(const float4*)&stg[r * 132 + c4];
    }
}

// ---------------- write path (unchanged, passing) ----------------
__global__ __launch_bounds__(256, 1)
void write_kernel(const float* __restrict__ gk, const float* __restrict__ gv,
                  const float* __restrict__ slot_keys, float* __restrict__ gslot) {
    __shared__ float sk[64 * 65];
    __shared__ float kvs[8][2][64];

    const int b = blockIdx.z, h = blockIdx.y, chunk = blockIdx.x;
    const int tid = threadIdx.x, w = tid >> 5, l = tid & 31;

    for (int idx = tid; idx < 4096; idx += 256) {
        int s = idx >> 6, d = idx & 63;
        sk[s * 65 + d] = slot_keys[((size_t)h * 64 + s) * 64 + d];
    }
    __syncthreads();

    float accL[64], accH[64];
#pragma unroll
    for (int d = 0; d < 64; d++) { accL[d] = 0.0f; accH[d] = 0.0f; }

    const float* skL = &sk[l * 65];
    const float* skH = &sk[(l + 32) * 65];
    const int t0 = chunk * 512 + w * 64;

    for (int tt = 0; tt < 64; tt++) {
        int t = t0 + tt;
        size_t row = ((size_t)b * Tc + t) * 1024 + h * 64;
        kvs[w][0][l] = gk[row + l];       kvs[w][0][l + 32] = gk[row + l + 32];
        kvs[w][1][l] = gv[row + l];       kvs[w][1][l + 32] = gv[row + l + 32];
        __syncwarp();

        float lo = 0.0f, hi = 0.0f;
#pragma unroll
        for (int d = 0; d < 64; d++) {
            float kd = kvs[w][0][d];
            lo += kd * skL[d];
            hi += kd * skH[d];
        }
        lo *= 0.125f; hi *= 0.125f;

        float mx = fmaxf(lo, hi);
#pragma unroll
        for (int off = 16; off; off >>= 1) mx = fmaxf(mx, __shfl_xor_sync(0xffffffffu, mx, off));
        float el = __expf(lo - mx), eh = __expf(hi - mx);
        float sm = el + eh;
#pragma unroll
        for (int off = 16; off; off >>= 1) sm += __shfl_xor_sync(0xffffffffu, sm, off);
        float inv = 1.0f / sm;
        float wl = el * inv, wh = eh * inv;

#pragma unroll
        for (int d = 0; d < 64; d++) {
            float vd = kvs[w][1][d];
            accL[d] += wl * vd;
            accH[d] += wh * vd;
        }
        __syncwarp();
    }

    __syncthreads();
    for (int idx = tid; idx < 64 * 65; idx += 256) sk[idx] = 0.0f;
    __syncthreads();
#pragma unroll
    for (int d = 0; d < 64; d++) {
        atomicAdd(&sk[l * 65 + d], accL[d]);
        atomicAdd(&sk[(l + 32) * 65 + d], accH[d]);
    }
    __syncthreads();
    float* base = gslot + ((size_t)(b * Hc + h)) * 4096;
    for (int idx = tid; idx < 4096; idx += 256) {
        int s = idx >> 6, d = idx & 63;
        atomicAdd(&base[idx], sk[s * 65 + d]);
    }
}

// ---------------- read path (unchanged, passing) ----------------
__global__ __launch_bounds__(256, 2)
void read_kernel(const float* __restrict__ gq, const float* __restrict__ gslot,
                 float* __restrict__ gro) {
    __shared__ float ss[64 * 65];
    __shared__ float qs[8][64];
    __shared__ float ws[8][64];

    const int b = blockIdx.z, h = blockIdx.y, chunk = blockIdx.x;
    const int tid = threadIdx.x, w = tid >> 5, l = tid & 31;

    const float* base = gslot + ((size_t)(b * Hc + h)) * 4096;
    const float invT = 1.0f / (float)Tc;
    for (int idx = tid; idx < 4096; idx += 256) {
        int s = idx >> 6, d = idx & 63;
        ss[s * 65 + d] = base[idx] * invT;
    }
    __syncthreads();

    const float* ssL = &ss[l * 65];
    const float* ssH = &ss[(l + 32) * 65];
    const int t0 = chunk * 512 + w * 64;

    for (int tt = 0; tt < 64; tt++) {
        int t = t0 + tt;
        size_t row = ((size_t)b * Tc + t) * 1024 + h * 64;
        qs[w][l] = gq[row + l];  qs[w][l + 32] = gq[row + l + 32];
        __syncwarp();

        float lo = 0.0f, hi = 0.0f;
#pragma unroll
        for (int d = 0; d < 64; d++) {
            float qd = qs[w][d];
            lo += qd * ssL[d];
            hi += qd * ssH[d];
        }
        lo *= 0.125f; hi *= 0.125f;

        float mx = fmaxf(lo, hi);
#pragma unroll
        for (int off = 16; off; off >>= 1) mx = fmaxf(mx, __shfl_xor_sync(0xffffffffu, mx, off));
        float el = __expf(lo - mx), eh = __expf(hi - mx);
        float sm = el + eh;
#pragma unroll
        for (int off = 16; off; off >>= 1) sm += __shfl_xor_sync(0xffffffffu, sm, off);
        float inv = 1.0f / sm;
        ws[w][l] = el * inv;  ws[w][l + 32] = eh * inv;
        __syncwarp();

        float oL = 0.0f, oH = 0.0f;
#pragma unroll
        for (int s = 0; s < 64; s++) {
            float wv = ws[w][s];
            oL += wv * ss[s * 65 + l];
            oH += wv * ss[s * 65 + l + 32];
        }
        gro[row + l] = oL;
        gro[row + l + 32] = oH;
        __syncwarp();
    }
}

// ---------------- launch ----------------
extern "C" void kernel_launch(void* const* d_in, const int* in_sizes, int n_in,
                              void* d_out, int out_size) {
    (void)in_sizes; (void)n_in; (void)out_size;
    const float* x         = (const float*)d_in[0];
    const float* Wq        = (const float*)d_in[1];
    const float* Wk        = (const float*)d_in[2];
    const float* Wv        = (const float*)d_in[3];
    const float* Wout      = (const float*)d_in[4];
    const float* slot_keys = (const float*)d_in[5];
    float* out = (float*)d_out;

    float *pq, *pk, *pv, *pro, *pslot, *pcos, *psin;
    cudaGetSymbolAddress((void**)&pq,    g_q);
    cudaGetSymbolAddress((void**)&pk,    g_k);
    cudaGetSymbolAddress((void**)&pv,    g_v);
    cudaGetSymbolAddress((void**)&pro,   g_ro);
    cudaGetSymbolAddress((void**)&pslot, g_slot);
    cudaGetSymbolAddress((void**)&pcos,  g_cos);
    cudaGetSymbolAddress((void**)&psin,  g_sin);

    __half *xf, *wf;
    __nv_bfloat16 *rohi, *rolo, *whi, *wlo;
    cudaGetSymbolAddress((void**)&xf,   g_xf);
    cudaGetSymbolAddress((void**)&wf,   g_wf);
    cudaGetSymbolAddress((void**)&rohi, g_rohi);
    cudaGetSymbolAddress((void**)&rolo, g_rolo);
    cudaGetSymbolAddress((void**)&whi,  g_whi);
    cudaGetSymbolAddress((void**)&wlo,  g_wlo);
    const size_t WSZ = (size_t)Ec * Ec;

    cudaFuncSetAttribute(gemm1<0>, cudaFuncAttributeMaxDynamicSharedMemorySize, GEMM1_SMEM);
    cudaFuncSetAttribute(gemm1<1>, cudaFuncAttributeMaxDynamicSharedMemorySize, GEMM1_SMEM);
    cudaFuncSetAttribute(gemm3, cudaFuncAttributeMaxDynamicSharedMemorySize, GEMM3_SMEM);

    rope_table_kernel<<<Tc, 32>>>(pcos, psin);

    // fp16 converts for QKV
    cvt_f16_kernel<<<(Mc * Ec / 4 + 255) / 256, 256>>>(x, xf, Mc * Ec / 4);
    cvt_f16_kernel<<<(int)(WSZ / 4 + 255) / 256, 256>>>(Wq, wf + 0 * WSZ, (int)(WSZ / 4));
    cvt_f16_kernel<<<(int)(WSZ / 4 + 255) / 256, 256>>>(Wk, wf + 1 * WSZ, (int)(WSZ / 4));
    cvt_f16_kernel<<<(int)(WSZ / 4 + 255) / 256, 256>>>(Wv, wf + 2 * WSZ, (int)(WSZ / 4));
    // bf16 split for Wout
    split_kernel<<<(int)(WSZ / 4 + 255) / 256, 256>>>(Wout, whi, wlo, (int)(WSZ / 4));

    dim3 gg(Ec / 128, Mc / 128);   // (8, 128)
    gemm1<1><<<gg, 256, GEMM1_SMEM>>>(xf, wf + 0 * WSZ, pq, pcos, psin);
    gemm1<1><<<gg, 256, GEMM1_SMEM>>>(xf, wf + 1 * WSZ, pk, pcos, psin);
    gemm1<0><<<gg, 256, GEMM1_SMEM>>>(xf, wf + 2 * WSZ, pv, pcos, psin);

    zero_kernel<<<(Bc * Hc * Sc * Dc + 255) / 256, 256>>>(pslot, Bc * Hc * Sc * Dc);

    write_kernel<<<dim3(8, Hc, Bc), 256>>>(pk, pv, slot_keys, pslot);
    read_kernel<<<dim3(8, Hc, Bc), 256>>>(pq, pslot, pro);

    split_kernel<<<(Mc * Ec / 4 + 255) / 256, 256>>>(pro, rohi, rolo, Mc * Ec / 4);
    gemm3<<<gg, 256, GEMM3_SMEM>>>(rohi, rolo, whi, wlo, out);
}